// round 1
// baseline (speedup 1.0000x reference)
#include <cuda_runtime.h>
#include <math.h>

#define MAX_N 100000
#define D 64
#define TWO_D 128

// Scratch (static __device__ arrays — no allocations allowed)
__device__ float4 g_gate[MAX_N];                       // (low_dst, low_src, high_dst, high_src) per node
__device__ float  g_z[(size_t)MAX_N * TWO_D];          // [N, 2D] aggregation buffer (z_low | z_high)

// ---------------------------------------------------------------------------
// Kernel 1: per-node gate projections. One warp per node.
// low_dst[n] = h[n]·Wl[:D], low_src[n] = h[n]·Wl[D:], same for Wh.
// ---------------------------------------------------------------------------
__global__ void gate_kernel(const float* __restrict__ h,
                            const float* __restrict__ Wl,
                            const float* __restrict__ Wh,
                            int n)
{
    int warp = (blockIdx.x * blockDim.x + threadIdx.x) >> 5;
    int lane = threadIdx.x & 31;
    if (warp >= n) return;

    const float* hp = h + (size_t)warp * D;
    float a0 = hp[lane];
    float a1 = hp[lane + 32];

    float ld = a0 * Wl[lane]      + a1 * Wl[lane + 32];
    float ls = a0 * Wl[lane + 64] + a1 * Wl[lane + 96];
    float hd = a0 * Wh[lane]      + a1 * Wh[lane + 32];
    float hs = a0 * Wh[lane + 64] + a1 * Wh[lane + 96];

    #pragma unroll
    for (int off = 16; off; off >>= 1) {
        ld += __shfl_xor_sync(0xFFFFFFFFu, ld, off);
        ls += __shfl_xor_sync(0xFFFFFFFFu, ls, off);
        hd += __shfl_xor_sync(0xFFFFFFFFu, hd, off);
        hs += __shfl_xor_sync(0xFFFFFFFFu, hs, off);
    }
    if (lane == 0) g_gate[warp] = make_float4(ld, ls, hd, hs);
}

// ---------------------------------------------------------------------------
// Kernel 2: zero the aggregation buffer (d_out/z poisoned each run).
// ---------------------------------------------------------------------------
__global__ void zero_kernel(size_t total4)
{
    size_t i = (size_t)blockIdx.x * blockDim.x + threadIdx.x;
    size_t stride = (size_t)gridDim.x * blockDim.x;
    float4* z4 = reinterpret_cast<float4*>(g_z);
    for (; i < total4; i += stride)
        z4[i] = make_float4(0.f, 0.f, 0.f, 0.f);
}

// ---------------------------------------------------------------------------
// Kernel 3: edge scatter. One warp per edge.
//   _low  = low_dst[dst] + low_src[src] + bl ; g_low  =  tanh(leaky(_low))
//   _high = high_dst[dst]+ high_src[src]+ bh ; g_high = -tanh(leaky(_high))
//   z_low[dst]  += h[src] * g_low  * d[dst]*d[src]
//   z_high[dst] += h[src] * g_high * d[dst]*d[src]
// ---------------------------------------------------------------------------
__global__ void edge_kernel(const float* __restrict__ h,
                            const float* __restrict__ dnorm,
                            const int*   __restrict__ src,
                            const int*   __restrict__ dst,
                            const float* __restrict__ bl,
                            const float* __restrict__ bh,
                            int e)
{
    int warp = (blockIdx.x * blockDim.x + threadIdx.x) >> 5;
    int lane = threadIdx.x & 31;
    if (warp >= e) return;

    int s = src[warp];
    int t = dst[warp];

    float4 gs = g_gate[s];
    float4 gt = g_gate[t];

    float xl = gt.x + gs.y + bl[0];
    float xh = gt.z + gs.w + bh[0];
    // where(x>0, x, -0.5x) is >= 0 so relu is identity
    float gl =  tanhf(xl > 0.f ? xl : -0.5f * xl);
    float gh = -tanhf(xh > 0.f ? xh : -0.5f * xh);

    float dd = dnorm[t] * dnorm[s];
    float el = gl * dd;
    float eh = gh * dd;

    const float* hs = h + (size_t)s * D;
    float* z = g_z + (size_t)t * TWO_D;

    float h0 = hs[lane];
    float h1 = hs[lane + 32];

    atomicAdd(z + lane,          h0 * el);
    atomicAdd(z + lane + 32,     h1 * el);
    atomicAdd(z + D + lane,      h0 * eh);
    atomicAdd(z + D + lane + 32, h1 * eh);
}

// ---------------------------------------------------------------------------
// Kernel 4: output projection. out[n,j] = sum_k z[n,k] * Wr[j,k] + br[j]
// Block: (64, 4) threads = 4 nodes per block, Wr transposed in shared.
// ---------------------------------------------------------------------------
__global__ void out_kernel(const float* __restrict__ Wr,
                           const float* __restrict__ br,
                           float* __restrict__ out,
                           int n)
{
    __shared__ float sW[TWO_D][D];   // sW[k][j] = Wr[j*128 + k]
    __shared__ float sZ[4][TWO_D];

    int tid = threadIdx.y * 64 + threadIdx.x;   // 0..255

    for (int i = tid; i < D * TWO_D; i += 256) {
        int j = i / TWO_D;
        int k = i % TWO_D;
        sW[k][j] = Wr[i];
    }

    int node0 = blockIdx.x * 4;
    for (int i = tid; i < 4 * TWO_D; i += 256) {
        int nn = node0 + i / TWO_D;
        sZ[i / TWO_D][i % TWO_D] = (nn < n) ? g_z[(size_t)nn * TWO_D + (i % TWO_D)] : 0.f;
    }
    __syncthreads();

    int node = node0 + threadIdx.y;
    if (node >= n) return;

    int j = threadIdx.x;
    float acc = br[j];
    #pragma unroll
    for (int k = 0; k < TWO_D; k++)
        acc = fmaf(sZ[threadIdx.y][k], sW[k][j], acc);

    out[(size_t)node * D + j] = acc;
}

// ---------------------------------------------------------------------------
extern "C" void kernel_launch(void* const* d_in, const int* in_sizes, int n_in,
                              void* d_out, int out_size)
{
    const float* h   = (const float*)d_in[0];
    const float* dn  = (const float*)d_in[1];
    const int*   src = (const int*)  d_in[2];
    const int*   dst = (const int*)  d_in[3];
    const float* Wl  = (const float*)d_in[4];
    const float* bl  = (const float*)d_in[5];
    const float* Wh  = (const float*)d_in[6];
    const float* bh  = (const float*)d_in[7];
    const float* Wr  = (const float*)d_in[8];
    const float* br  = (const float*)d_in[9];
    float* out = (float*)d_out;

    int n = in_sizes[0] / D;      // nodes
    int e = in_sizes[2];          // edges

    // 1. zero z
    size_t total4 = ((size_t)n * TWO_D) / 4;
    zero_kernel<<<1184, 256>>>(total4);   // 8 blocks/SM grid-stride

    // 2. gates (one warp per node)
    gate_kernel<<<(n * 32 + 255) / 256, 256>>>(h, Wl, Wh, n);

    // 3. edge scatter (one warp per edge)
    edge_kernel<<<((size_t)e * 32 + 255) / 256, 256>>>(h, dn, src, dst, bl, bh, e);

    // 4. output projection
    dim3 blk(64, 4);
    out_kernel<<<(n + 3) / 4, blk>>>(Wr, br, out, n);
}

// round 2
// speedup vs baseline: 3.8293x; 3.8293x over previous
#include <cuda_runtime.h>
#include <math.h>

#define MAX_N 100000
#define D 64
#define TWO_D 128
#define NB 64          // nodes per block in out_kernel

// Scratch (static __device__ arrays — no allocations allowed)
__device__ float4 g_gate[MAX_N];                       // (low_dst, low_src, high_dst, high_src)
__device__ float  g_z[(size_t)MAX_N * TWO_D];          // [N, 2D] aggregation (z_low | z_high)
__device__ float  g_WrT[TWO_D * D];                    // Wr transposed: [k][j] = Wr[j][k]

// ---------------------------------------------------------------------------
// Kernel 0: transpose Wr [64,128] -> g_WrT [128,64] (one-time tiny kernel)
// ---------------------------------------------------------------------------
__global__ void wt_kernel(const float* __restrict__ Wr)
{
    int i = blockIdx.x * blockDim.x + threadIdx.x;
    if (i < D * TWO_D) {
        int j = i >> 7;           // row of Wr (0..63)
        int k = i & 127;          // col of Wr (0..127)
        g_WrT[k * D + j] = Wr[i];
    }
}

// ---------------------------------------------------------------------------
// Kernel 1: per-node gate projections. One warp per node.
// ---------------------------------------------------------------------------
__global__ void gate_kernel(const float* __restrict__ h,
                            const float* __restrict__ Wl,
                            const float* __restrict__ Wh,
                            int n)
{
    int warp = (blockIdx.x * blockDim.x + threadIdx.x) >> 5;
    int lane = threadIdx.x & 31;
    if (warp >= n) return;

    const float* hp = h + (size_t)warp * D;
    float a0 = hp[lane];
    float a1 = hp[lane + 32];

    float ld = a0 * Wl[lane]      + a1 * Wl[lane + 32];
    float ls = a0 * Wl[lane + 64] + a1 * Wl[lane + 96];
    float hd = a0 * Wh[lane]      + a1 * Wh[lane + 32];
    float hs = a0 * Wh[lane + 64] + a1 * Wh[lane + 96];

    #pragma unroll
    for (int off = 16; off; off >>= 1) {
        ld += __shfl_xor_sync(0xFFFFFFFFu, ld, off);
        ls += __shfl_xor_sync(0xFFFFFFFFu, ls, off);
        hd += __shfl_xor_sync(0xFFFFFFFFu, hd, off);
        hs += __shfl_xor_sync(0xFFFFFFFFu, hs, off);
    }
    if (lane == 0) g_gate[warp] = make_float4(ld, ls, hd, hs);
}

// ---------------------------------------------------------------------------
// Kernel 2: zero the aggregation buffer.
// ---------------------------------------------------------------------------
__global__ void zero_kernel(size_t total4)
{
    size_t i = (size_t)blockIdx.x * blockDim.x + threadIdx.x;
    size_t stride = (size_t)gridDim.x * blockDim.x;
    float4* z4 = reinterpret_cast<float4*>(g_z);
    for (; i < total4; i += stride)
        z4[i] = make_float4(0.f, 0.f, 0.f, 0.f);
}

// ---------------------------------------------------------------------------
// Kernel 3: edge scatter. One warp per edge.
// ---------------------------------------------------------------------------
__global__ void edge_kernel(const float* __restrict__ h,
                            const float* __restrict__ dnorm,
                            const int*   __restrict__ src,
                            const int*   __restrict__ dst,
                            const float* __restrict__ bl,
                            const float* __restrict__ bh,
                            int e)
{
    int warp = (blockIdx.x * blockDim.x + threadIdx.x) >> 5;
    int lane = threadIdx.x & 31;
    if (warp >= e) return;

    int s = src[warp];
    int t = dst[warp];

    float4 gs = g_gate[s];
    float4 gt = g_gate[t];

    float xl = gt.x + gs.y + bl[0];
    float xh = gt.z + gs.w + bh[0];
    float gl =  tanhf(xl > 0.f ? xl : -0.5f * xl);
    float gh = -tanhf(xh > 0.f ? xh : -0.5f * xh);

    float dd = dnorm[t] * dnorm[s];
    float el = gl * dd;
    float eh = gh * dd;

    const float* hs = h + (size_t)s * D;
    float* z = g_z + (size_t)t * TWO_D;

    float h0 = hs[lane];
    float h1 = hs[lane + 32];

    atomicAdd(z + lane,          h0 * el);
    atomicAdd(z + lane + 32,     h1 * el);
    atomicAdd(z + D + lane,      h0 * eh);
    atomicAdd(z + D + lane + 32, h1 * eh);
}

// ---------------------------------------------------------------------------
// Kernel 4: output projection, register-blocked 4x4.
// Block: 256 threads, NB=64 nodes. out[n,j] = sum_k z[n,k]*WrT[k,j] + br[j]
// ---------------------------------------------------------------------------
__global__ void __launch_bounds__(256) out_kernel(const float* __restrict__ br,
                                                  float* __restrict__ out,
                                                  int n)
{
    __shared__ float sW[TWO_D * D];    // [k][j], 32 KB
    __shared__ float sZ[NB * TWO_D];   // [node][k], 32 KB

    int tid = threadIdx.x;
    int node0 = blockIdx.x * NB;

    // Stage W: coalesced global read, contiguous shared write (conflict-free)
    {
        const float4* Wg = reinterpret_cast<const float4*>(g_WrT);
        float4* Ws = reinterpret_cast<float4*>(sW);
        #pragma unroll
        for (int i = tid; i < (TWO_D * D) / 4; i += 256)
            Ws[i] = Wg[i];
    }
    // Stage Z: 64 nodes x 128 floats, coalesced
    {
        const float4* Zg = reinterpret_cast<const float4*>(g_z) + (size_t)node0 * (TWO_D / 4);
        float4* Zs = reinterpret_cast<float4*>(sZ);
        #pragma unroll
        for (int i = tid; i < NB * (TWO_D / 4); i += 256) {
            int node = node0 + i / (TWO_D / 4);
            Zs[i] = (node < n) ? Zg[i] : make_float4(0.f, 0.f, 0.f, 0.f);
        }
    }
    __syncthreads();

    int jg = tid & 15;        // j-group: j = jg*4 .. jg*4+3
    int ng = tid >> 4;        // node-group: nodes ng*4 .. ng*4+3

    float acc[4][4];
    #pragma unroll
    for (int i = 0; i < 4; i++)
        #pragma unroll
        for (int jj = 0; jj < 4; jj++)
            acc[i][jj] = 0.f;

    const float4* sW4 = reinterpret_cast<const float4*>(sW);
    const float* zbase = sZ + ng * 4 * TWO_D;

    #pragma unroll 4
    for (int k = 0; k < TWO_D; k++) {
        float4 w = sW4[k * (D / 4) + jg];
        float z0 = zbase[0 * TWO_D + k];
        float z1 = zbase[1 * TWO_D + k];
        float z2 = zbase[2 * TWO_D + k];
        float z3 = zbase[3 * TWO_D + k];
        acc[0][0] = fmaf(z0, w.x, acc[0][0]); acc[0][1] = fmaf(z0, w.y, acc[0][1]);
        acc[0][2] = fmaf(z0, w.z, acc[0][2]); acc[0][3] = fmaf(z0, w.w, acc[0][3]);
        acc[1][0] = fmaf(z1, w.x, acc[1][0]); acc[1][1] = fmaf(z1, w.y, acc[1][1]);
        acc[1][2] = fmaf(z1, w.z, acc[1][2]); acc[1][3] = fmaf(z1, w.w, acc[1][3]);
        acc[2][0] = fmaf(z2, w.x, acc[2][0]); acc[2][1] = fmaf(z2, w.y, acc[2][1]);
        acc[2][2] = fmaf(z2, w.z, acc[2][2]); acc[2][3] = fmaf(z2, w.w, acc[2][3]);
        acc[3][0] = fmaf(z3, w.x, acc[3][0]); acc[3][1] = fmaf(z3, w.y, acc[3][1]);
        acc[3][2] = fmaf(z3, w.z, acc[3][2]); acc[3][3] = fmaf(z3, w.w, acc[3][3]);
    }

    int j = jg * 4;
    float4 b4 = *reinterpret_cast<const float4*>(br + j);
    #pragma unroll
    for (int i = 0; i < 4; i++) {
        int node = node0 + ng * 4 + i;
        if (node < n) {
            float4 o;
            o.x = acc[i][0] + b4.x;
            o.y = acc[i][1] + b4.y;
            o.z = acc[i][2] + b4.z;
            o.w = acc[i][3] + b4.w;
            *reinterpret_cast<float4*>(out + (size_t)node * D + j) = o;
        }
    }
}

// ---------------------------------------------------------------------------
extern "C" void kernel_launch(void* const* d_in, const int* in_sizes, int n_in,
                              void* d_out, int out_size)
{
    const float* h   = (const float*)d_in[0];
    const float* dn  = (const float*)d_in[1];
    const int*   src = (const int*)  d_in[2];
    const int*   dst = (const int*)  d_in[3];
    const float* Wl  = (const float*)d_in[4];
    const float* bl  = (const float*)d_in[5];
    const float* Wh  = (const float*)d_in[6];
    const float* bh  = (const float*)d_in[7];
    const float* Wr  = (const float*)d_in[8];
    const float* br  = (const float*)d_in[9];
    float* out = (float*)d_out;

    int n = in_sizes[0] / D;      // nodes
    int e = in_sizes[2];          // edges

    // 0. transpose Wr
    wt_kernel<<<(D * TWO_D + 255) / 256, 256>>>(Wr);

    // 1. zero z
    size_t total4 = ((size_t)n * TWO_D) / 4;
    zero_kernel<<<1184, 256>>>(total4);

    // 2. gates (one warp per node)
    gate_kernel<<<(n * 32 + 255) / 256, 256>>>(h, Wl, Wh, n);

    // 3. edge scatter (one warp per edge)
    edge_kernel<<<((size_t)e * 32 + 255) / 256, 256>>>(h, dn, src, dst, bl, bh, e);

    // 4. output projection
    out_kernel<<<(n + NB - 1) / NB, 256>>>(br, out, n);
}

// round 3
// speedup vs baseline: 3.8789x; 1.0129x over previous
#include <cuda_runtime.h>
#include <math.h>

#define MAX_N 100000
#define MAX_E 1600000
#define D 64
#define TWO_D 128
#define NB 64          // nodes per block in out_kernel

// Scratch (static __device__ arrays — no allocations allowed)
__device__ float4 g_gate[MAX_N];                       // (low_dst, low_src, high_dst, high_src)
__device__ float  g_z[(size_t)MAX_N * TWO_D];          // [N, 2D] aggregation (z_low | z_high)
__device__ float  g_WrT[TWO_D * D];                    // Wr transposed: [k][j] = Wr[j][k]
__device__ float2 g_coef[MAX_E];                       // per-edge (e_low, e_high)

// ---------------------------------------------------------------------------
// Kernel 0: transpose Wr [64,128] -> g_WrT [128,64]
// ---------------------------------------------------------------------------
__global__ void wt_kernel(const float* __restrict__ Wr)
{
    int i = blockIdx.x * blockDim.x + threadIdx.x;
    if (i < D * TWO_D) {
        int j = i >> 7;
        int k = i & 127;
        g_WrT[k * D + j] = Wr[i];
    }
}

// ---------------------------------------------------------------------------
// Kernel 1: per-node gate projections. One warp per node.
// ---------------------------------------------------------------------------
__global__ void gate_kernel(const float* __restrict__ h,
                            const float* __restrict__ Wl,
                            const float* __restrict__ Wh,
                            int n)
{
    int warp = (blockIdx.x * blockDim.x + threadIdx.x) >> 5;
    int lane = threadIdx.x & 31;
    if (warp >= n) return;

    const float* hp = h + (size_t)warp * D;
    float a0 = hp[lane];
    float a1 = hp[lane + 32];

    float ld = a0 * Wl[lane]      + a1 * Wl[lane + 32];
    float ls = a0 * Wl[lane + 64] + a1 * Wl[lane + 96];
    float hd = a0 * Wh[lane]      + a1 * Wh[lane + 32];
    float hs = a0 * Wh[lane + 64] + a1 * Wh[lane + 96];

    #pragma unroll
    for (int off = 16; off; off >>= 1) {
        ld += __shfl_xor_sync(0xFFFFFFFFu, ld, off);
        ls += __shfl_xor_sync(0xFFFFFFFFu, ls, off);
        hd += __shfl_xor_sync(0xFFFFFFFFu, hd, off);
        hs += __shfl_xor_sync(0xFFFFFFFFu, hs, off);
    }
    if (lane == 0) g_gate[warp] = make_float4(ld, ls, hd, hs);
}

// ---------------------------------------------------------------------------
// Kernel 2: zero the aggregation buffer.
// ---------------------------------------------------------------------------
__global__ void zero_kernel(size_t total4)
{
    size_t i = (size_t)blockIdx.x * blockDim.x + threadIdx.x;
    size_t stride = (size_t)gridDim.x * blockDim.x;
    float4* z4 = reinterpret_cast<float4*>(g_z);
    for (; i < total4; i += stride)
        z4[i] = make_float4(0.f, 0.f, 0.f, 0.f);
}

// ---------------------------------------------------------------------------
// Kernel 3a: per-edge coefficients. One THREAD per edge (no redundancy).
// ---------------------------------------------------------------------------
__global__ void coef_kernel(const float* __restrict__ dnorm,
                            const int*   __restrict__ src,
                            const int*   __restrict__ dst,
                            const float* __restrict__ bl,
                            const float* __restrict__ bh,
                            int e)
{
    int i = blockIdx.x * blockDim.x + threadIdx.x;
    if (i >= e) return;

    int s = src[i];
    int t = dst[i];

    float4 gs = g_gate[s];
    float4 gt = g_gate[t];

    float xl = gt.x + gs.y + bl[0];
    float xh = gt.z + gs.w + bh[0];
    float gl =  tanhf(xl > 0.f ? xl : -0.5f * xl);
    float gh = -tanhf(xh > 0.f ? xh : -0.5f * xh);

    float dd = dnorm[t] * dnorm[s];
    g_coef[i] = make_float2(gl * dd, gh * dd);
}

// ---------------------------------------------------------------------------
// Kernel 3b: edge scatter. One warp per edge, one red.v4 per lane.
// Lanes 0-15 cover z_low[0..63], lanes 16-31 cover z_high[0..63].
// ---------------------------------------------------------------------------
__global__ void scatter_kernel(const float* __restrict__ h,
                               const int*   __restrict__ src,
                               const int*   __restrict__ dst,
                               int e)
{
    int warp = (blockIdx.x * blockDim.x + threadIdx.x) >> 5;
    int lane = threadIdx.x & 31;
    if (warp >= e) return;

    int s = src[warp];
    int t = dst[warp];
    float2 c = g_coef[warp];

    // h row as float4s: lane&15 selects which 16B chunk (both halves load same)
    const float4* h4 = reinterpret_cast<const float4*>(h + (size_t)s * D);
    float4 hv = h4[lane & 15];

    float cc = (lane < 16) ? c.x : c.y;
    float4 v;
    v.x = hv.x * cc; v.y = hv.y * cc; v.z = hv.z * cc; v.w = hv.w * cc;

    float* z = g_z + (size_t)t * TWO_D + lane * 4;
    asm volatile("red.global.add.v4.f32 [%0], {%1, %2, %3, %4};"
                 :: "l"(z), "f"(v.x), "f"(v.y), "f"(v.z), "f"(v.w)
                 : "memory");
}

// ---------------------------------------------------------------------------
// Kernel 4: output projection, register-blocked 4x4.
// ---------------------------------------------------------------------------
__global__ void __launch_bounds__(256) out_kernel(const float* __restrict__ br,
                                                  float* __restrict__ out,
                                                  int n)
{
    __shared__ float sW[TWO_D * D];    // [k][j], 32 KB
    __shared__ float sZ[NB * TWO_D];   // [node][k], 32 KB

    int tid = threadIdx.x;
    int node0 = blockIdx.x * NB;

    {
        const float4* Wg = reinterpret_cast<const float4*>(g_WrT);
        float4* Ws = reinterpret_cast<float4*>(sW);
        #pragma unroll
        for (int i = tid; i < (TWO_D * D) / 4; i += 256)
            Ws[i] = Wg[i];
    }
    {
        const float4* Zg = reinterpret_cast<const float4*>(g_z) + (size_t)node0 * (TWO_D / 4);
        float4* Zs = reinterpret_cast<float4*>(sZ);
        #pragma unroll
        for (int i = tid; i < NB * (TWO_D / 4); i += 256) {
            int node = node0 + i / (TWO_D / 4);
            Zs[i] = (node < n) ? Zg[i] : make_float4(0.f, 0.f, 0.f, 0.f);
        }
    }
    __syncthreads();

    int jg = tid & 15;
    int ng = tid >> 4;

    float acc[4][4];
    #pragma unroll
    for (int i = 0; i < 4; i++)
        #pragma unroll
        for (int jj = 0; jj < 4; jj++)
            acc[i][jj] = 0.f;

    const float4* sW4 = reinterpret_cast<const float4*>(sW);
    const float* zbase = sZ + ng * 4 * TWO_D;

    #pragma unroll 4
    for (int k = 0; k < TWO_D; k++) {
        float4 w = sW4[k * (D / 4) + jg];
        float z0 = zbase[0 * TWO_D + k];
        float z1 = zbase[1 * TWO_D + k];
        float z2 = zbase[2 * TWO_D + k];
        float z3 = zbase[3 * TWO_D + k];
        acc[0][0] = fmaf(z0, w.x, acc[0][0]); acc[0][1] = fmaf(z0, w.y, acc[0][1]);
        acc[0][2] = fmaf(z0, w.z, acc[0][2]); acc[0][3] = fmaf(z0, w.w, acc[0][3]);
        acc[1][0] = fmaf(z1, w.x, acc[1][0]); acc[1][1] = fmaf(z1, w.y, acc[1][1]);
        acc[1][2] = fmaf(z1, w.z, acc[1][2]); acc[1][3] = fmaf(z1, w.w, acc[1][3]);
        acc[2][0] = fmaf(z2, w.x, acc[2][0]); acc[2][1] = fmaf(z2, w.y, acc[2][1]);
        acc[2][2] = fmaf(z2, w.z, acc[2][2]); acc[2][3] = fmaf(z2, w.w, acc[2][3]);
        acc[3][0] = fmaf(z3, w.x, acc[3][0]); acc[3][1] = fmaf(z3, w.y, acc[3][1]);
        acc[3][2] = fmaf(z3, w.z, acc[3][2]); acc[3][3] = fmaf(z3, w.w, acc[3][3]);
    }

    int j = jg * 4;
    float4 b4 = *reinterpret_cast<const float4*>(br + j);
    #pragma unroll
    for (int i = 0; i < 4; i++) {
        int node = node0 + ng * 4 + i;
        if (node < n) {
            float4 o;
            o.x = acc[i][0] + b4.x;
            o.y = acc[i][1] + b4.y;
            o.z = acc[i][2] + b4.z;
            o.w = acc[i][3] + b4.w;
            *reinterpret_cast<float4*>(out + (size_t)node * D + j) = o;
        }
    }
}

// ---------------------------------------------------------------------------
extern "C" void kernel_launch(void* const* d_in, const int* in_sizes, int n_in,
                              void* d_out, int out_size)
{
    const float* h   = (const float*)d_in[0];
    const float* dn  = (const float*)d_in[1];
    const int*   src = (const int*)  d_in[2];
    const int*   dst = (const int*)  d_in[3];
    const float* Wl  = (const float*)d_in[4];
    const float* bl  = (const float*)d_in[5];
    const float* Wh  = (const float*)d_in[6];
    const float* bh  = (const float*)d_in[7];
    const float* Wr  = (const float*)d_in[8];
    const float* br  = (const float*)d_in[9];
    float* out = (float*)d_out;

    int n = in_sizes[0] / D;      // nodes
    int e = in_sizes[2];          // edges

    // 0. transpose Wr
    wt_kernel<<<(D * TWO_D + 255) / 256, 256>>>(Wr);

    // 1. zero z
    size_t total4 = ((size_t)n * TWO_D) / 4;
    zero_kernel<<<1184, 256>>>(total4);

    // 2. gates (one warp per node)
    gate_kernel<<<(n * 32 + 255) / 256, 256>>>(h, Wl, Wh, n);

    // 3a. per-edge coefficients (one thread per edge)
    coef_kernel<<<(e + 255) / 256, 256>>>(dn, src, dst, bl, bh, e);

    // 3b. edge scatter (one warp per edge, vector atomics)
    scatter_kernel<<<(int)(((size_t)e * 32 + 255) / 256), 256>>>(h, src, dst, e);

    // 4. output projection
    out_kernel<<<(n + NB - 1) / NB, 256>>>(br, out, n);
}

// round 4
// speedup vs baseline: 5.6481x; 1.4561x over previous
#include <cuda_runtime.h>
#include <math.h>

#define MAX_N 100000
#define MAX_E 1600000
#define D 64
#define TWO_D 128
#define NB 64
#define SCAN_B 512

// Scratch (static __device__ arrays — no allocations allowed)
__device__ float4 g_gate[MAX_N];                 // (low_dst, low_src, high_dst, high_src)
__device__ float  g_z[(size_t)MAX_N * TWO_D];    // [N, 2D] aggregation (z_low | z_high)
__device__ float  g_WrT[TWO_D * D];              // Wr transposed
__device__ int    g_deg[MAX_N];                  // in-degree per node
__device__ int    g_start[MAX_N];                // CSR row start (exclusive scan)
__device__ int    g_cursor[MAX_N];               // fill cursors
__device__ int    g_bsum[(MAX_N + SCAN_B - 1) / SCAN_B + 1];
__device__ int    g_esrc[MAX_E];                 // dst-grouped src indices
__device__ float2 g_ecoef[MAX_E];                // dst-grouped (e_low, e_high)

// ---------------------------------------------------------------------------
__global__ void wt_kernel(const float* __restrict__ Wr)
{
    int i = blockIdx.x * blockDim.x + threadIdx.x;
    if (i < D * TWO_D) {
        int j = i >> 7;
        int k = i & 127;
        g_WrT[k * D + j] = Wr[i];
    }
}

// ---------------------------------------------------------------------------
// Gate projections: one warp per node.
// ---------------------------------------------------------------------------
__global__ void gate_kernel(const float* __restrict__ h,
                            const float* __restrict__ Wl,
                            const float* __restrict__ Wh,
                            int n)
{
    int warp = (blockIdx.x * blockDim.x + threadIdx.x) >> 5;
    int lane = threadIdx.x & 31;
    if (warp >= n) return;

    const float* hp = h + (size_t)warp * D;
    float a0 = hp[lane];
    float a1 = hp[lane + 32];

    float ld = a0 * Wl[lane]      + a1 * Wl[lane + 32];
    float ls = a0 * Wl[lane + 64] + a1 * Wl[lane + 96];
    float hd = a0 * Wh[lane]      + a1 * Wh[lane + 32];
    float hs = a0 * Wh[lane + 64] + a1 * Wh[lane + 96];

    #pragma unroll
    for (int off = 16; off; off >>= 1) {
        ld += __shfl_xor_sync(0xFFFFFFFFu, ld, off);
        ls += __shfl_xor_sync(0xFFFFFFFFu, ls, off);
        hd += __shfl_xor_sync(0xFFFFFFFFu, hd, off);
        hs += __shfl_xor_sync(0xFFFFFFFFu, hs, off);
    }
    if (lane == 0) g_gate[warp] = make_float4(ld, ls, hd, hs);
}

// ---------------------------------------------------------------------------
// CSR build: zero counters, histogram, 3-kernel exclusive scan, fill.
// ---------------------------------------------------------------------------
__global__ void zero_deg_kernel(int n)
{
    int i = blockIdx.x * blockDim.x + threadIdx.x;
    if (i < n) g_deg[i] = 0;
}

__global__ void hist_kernel(const int* __restrict__ dst, int e)
{
    int i = blockIdx.x * blockDim.x + threadIdx.x;
    if (i < e) atomicAdd(&g_deg[dst[i]], 1);
}

__global__ void scan1_kernel(int n)
{
    __shared__ int sh[SCAN_B];
    int tid = threadIdx.x;
    int i = blockIdx.x * SCAN_B + tid;
    int v = (i < n) ? g_deg[i] : 0;
    sh[tid] = v;
    __syncthreads();
    #pragma unroll
    for (int off = 1; off < SCAN_B; off <<= 1) {
        int t = (tid >= off) ? sh[tid - off] : 0;
        __syncthreads();
        sh[tid] += t;
        __syncthreads();
    }
    if (i < n) g_start[i] = sh[tid] - v;           // exclusive within block
    if (tid == SCAN_B - 1) g_bsum[blockIdx.x] = sh[tid];
}

__global__ void scan2_kernel(int nb)   // single block, 1024 threads
{
    __shared__ int sh[1024];
    int tid = threadIdx.x;
    int v = (tid < nb) ? g_bsum[tid] : 0;
    sh[tid] = v;
    __syncthreads();
    #pragma unroll
    for (int off = 1; off < 1024; off <<= 1) {
        int t = (tid >= off) ? sh[tid - off] : 0;
        __syncthreads();
        sh[tid] += t;
        __syncthreads();
    }
    if (tid < nb) g_bsum[tid] = sh[tid] - v;       // exclusive
}

__global__ void scan3_kernel(int n)
{
    int i = blockIdx.x * blockDim.x + threadIdx.x;
    if (i < n) {
        int s = g_start[i] + g_bsum[i / SCAN_B];
        g_start[i] = s;
        g_cursor[i] = s;
    }
}

// ---------------------------------------------------------------------------
// Fill: per-edge coef + CSR slot assignment (one thread per edge).
// ---------------------------------------------------------------------------
__global__ void fill_kernel(const float* __restrict__ dnorm,
                            const int*   __restrict__ src,
                            const int*   __restrict__ dst,
                            const float* __restrict__ bl,
                            const float* __restrict__ bh,
                            int e)
{
    int i = blockIdx.x * blockDim.x + threadIdx.x;
    if (i >= e) return;

    int s = src[i];
    int t = dst[i];

    float4 gs = g_gate[s];
    float4 gt = g_gate[t];

    float xl = gt.x + gs.y + bl[0];
    float xh = gt.z + gs.w + bh[0];
    float gl =  tanhf(xl > 0.f ? xl : -0.5f * xl);
    float gh = -tanhf(xh > 0.f ? xh : -0.5f * xh);

    float dd = dnorm[t] * dnorm[s];
    int pos = atomicAdd(&g_cursor[t], 1);
    g_esrc[pos] = s;
    g_ecoef[pos] = make_float2(gl * dd, gh * dd);
}

// ---------------------------------------------------------------------------
// Gather-aggregate: one warp per node, register accumulators, no atomics.
// Lane l owns h components l and l+32 for both low and high halves.
// ---------------------------------------------------------------------------
__global__ void gather_kernel(const float* __restrict__ h, int n)
{
    int warp = (blockIdx.x * blockDim.x + threadIdx.x) >> 5;
    int lane = threadIdx.x & 31;
    if (warp >= n) return;

    int start = g_start[warp];
    int deg   = g_deg[warp];
    int end   = start + deg;

    float zl0 = 0.f, zl1 = 0.f, zh0 = 0.f, zh1 = 0.f;

    for (int base = start; base < end; base += 32) {
        int my = base + lane;
        int msrc = 0;
        float2 mc = make_float2(0.f, 0.f);
        if (my < end) {
            msrc = g_esrc[my];
            mc   = g_ecoef[my];
        }
        int cnt = min(32, end - base);

        int i = 0;
        for (; i + 4 <= cnt; i += 4) {
            int s0 = __shfl_sync(0xFFFFFFFFu, msrc, i);
            int s1 = __shfl_sync(0xFFFFFFFFu, msrc, i + 1);
            int s2 = __shfl_sync(0xFFFFFFFFu, msrc, i + 2);
            int s3 = __shfl_sync(0xFFFFFFFFu, msrc, i + 3);
            float cl0 = __shfl_sync(0xFFFFFFFFu, mc.x, i);
            float ch0 = __shfl_sync(0xFFFFFFFFu, mc.y, i);
            float cl1 = __shfl_sync(0xFFFFFFFFu, mc.x, i + 1);
            float ch1 = __shfl_sync(0xFFFFFFFFu, mc.y, i + 1);
            float cl2 = __shfl_sync(0xFFFFFFFFu, mc.x, i + 2);
            float ch2 = __shfl_sync(0xFFFFFFFFu, mc.y, i + 2);
            float cl3 = __shfl_sync(0xFFFFFFFFu, mc.x, i + 3);
            float ch3 = __shfl_sync(0xFFFFFFFFu, mc.y, i + 3);

            const float* p0 = h + (size_t)s0 * D;
            const float* p1 = h + (size_t)s1 * D;
            const float* p2 = h + (size_t)s2 * D;
            const float* p3 = h + (size_t)s3 * D;
            float a0 = p0[lane], b0 = p0[lane + 32];
            float a1 = p1[lane], b1 = p1[lane + 32];
            float a2 = p2[lane], b2 = p2[lane + 32];
            float a3 = p3[lane], b3 = p3[lane + 32];

            zl0 = fmaf(a0, cl0, zl0); zl1 = fmaf(b0, cl0, zl1);
            zh0 = fmaf(a0, ch0, zh0); zh1 = fmaf(b0, ch0, zh1);
            zl0 = fmaf(a1, cl1, zl0); zl1 = fmaf(b1, cl1, zl1);
            zh0 = fmaf(a1, ch1, zh0); zh1 = fmaf(b1, ch1, zh1);
            zl0 = fmaf(a2, cl2, zl0); zl1 = fmaf(b2, cl2, zl1);
            zh0 = fmaf(a2, ch2, zh0); zh1 = fmaf(b2, ch2, zh1);
            zl0 = fmaf(a3, cl3, zl0); zl1 = fmaf(b3, cl3, zl1);
            zh0 = fmaf(a3, ch3, zh0); zh1 = fmaf(b3, ch3, zh1);
        }
        for (; i < cnt; i++) {
            int s0 = __shfl_sync(0xFFFFFFFFu, msrc, i);
            float cl = __shfl_sync(0xFFFFFFFFu, mc.x, i);
            float ch = __shfl_sync(0xFFFFFFFFu, mc.y, i);
            const float* p0 = h + (size_t)s0 * D;
            float a0 = p0[lane], b0 = p0[lane + 32];
            zl0 = fmaf(a0, cl, zl0); zl1 = fmaf(b0, cl, zl1);
            zh0 = fmaf(a0, ch, zh0); zh1 = fmaf(b0, ch, zh1);
        }
    }

    float* z = g_z + (size_t)warp * TWO_D;
    z[lane]      = zl0;
    z[lane + 32] = zl1;
    z[lane + 64] = zh0;
    z[lane + 96] = zh1;
}

// ---------------------------------------------------------------------------
// Output projection, register-blocked 4x4 (unchanged from R2).
// ---------------------------------------------------------------------------
__global__ void __launch_bounds__(256) out_kernel(const float* __restrict__ br,
                                                  float* __restrict__ out,
                                                  int n)
{
    __shared__ float sW[TWO_D * D];
    __shared__ float sZ[NB * TWO_D];

    int tid = threadIdx.x;
    int node0 = blockIdx.x * NB;

    {
        const float4* Wg = reinterpret_cast<const float4*>(g_WrT);
        float4* Ws = reinterpret_cast<float4*>(sW);
        #pragma unroll
        for (int i = tid; i < (TWO_D * D) / 4; i += 256)
            Ws[i] = Wg[i];
    }
    {
        const float4* Zg = reinterpret_cast<const float4*>(g_z) + (size_t)node0 * (TWO_D / 4);
        float4* Zs = reinterpret_cast<float4*>(sZ);
        #pragma unroll
        for (int i = tid; i < NB * (TWO_D / 4); i += 256) {
            int node = node0 + i / (TWO_D / 4);
            Zs[i] = (node < n) ? Zg[i] : make_float4(0.f, 0.f, 0.f, 0.f);
        }
    }
    __syncthreads();

    int jg = tid & 15;
    int ng = tid >> 4;

    float acc[4][4];
    #pragma unroll
    for (int i = 0; i < 4; i++)
        #pragma unroll
        for (int jj = 0; jj < 4; jj++)
            acc[i][jj] = 0.f;

    const float4* sW4 = reinterpret_cast<const float4*>(sW);
    const float* zbase = sZ + ng * 4 * TWO_D;

    #pragma unroll 4
    for (int k = 0; k < TWO_D; k++) {
        float4 w = sW4[k * (D / 4) + jg];
        float z0 = zbase[0 * TWO_D + k];
        float z1 = zbase[1 * TWO_D + k];
        float z2 = zbase[2 * TWO_D + k];
        float z3 = zbase[3 * TWO_D + k];
        acc[0][0] = fmaf(z0, w.x, acc[0][0]); acc[0][1] = fmaf(z0, w.y, acc[0][1]);
        acc[0][2] = fmaf(z0, w.z, acc[0][2]); acc[0][3] = fmaf(z0, w.w, acc[0][3]);
        acc[1][0] = fmaf(z1, w.x, acc[1][0]); acc[1][1] = fmaf(z1, w.y, acc[1][1]);
        acc[1][2] = fmaf(z1, w.z, acc[1][2]); acc[1][3] = fmaf(z1, w.w, acc[1][3]);
        acc[2][0] = fmaf(z2, w.x, acc[2][0]); acc[2][1] = fmaf(z2, w.y, acc[2][1]);
        acc[2][2] = fmaf(z2, w.z, acc[2][2]); acc[2][3] = fmaf(z2, w.w, acc[2][3]);
        acc[3][0] = fmaf(z3, w.x, acc[3][0]); acc[3][1] = fmaf(z3, w.y, acc[3][1]);
        acc[3][2] = fmaf(z3, w.z, acc[3][2]); acc[3][3] = fmaf(z3, w.w, acc[3][3]);
    }

    int j = jg * 4;
    float4 b4 = *reinterpret_cast<const float4*>(br + j);
    #pragma unroll
    for (int i = 0; i < 4; i++) {
        int node = node0 + ng * 4 + i;
        if (node < n) {
            float4 o;
            o.x = acc[i][0] + b4.x;
            o.y = acc[i][1] + b4.y;
            o.z = acc[i][2] + b4.z;
            o.w = acc[i][3] + b4.w;
            *reinterpret_cast<float4*>(out + (size_t)node * D + j) = o;
        }
    }
}

// ---------------------------------------------------------------------------
extern "C" void kernel_launch(void* const* d_in, const int* in_sizes, int n_in,
                              void* d_out, int out_size)
{
    const float* h   = (const float*)d_in[0];
    const float* dn  = (const float*)d_in[1];
    const int*   src = (const int*)  d_in[2];
    const int*   dst = (const int*)  d_in[3];
    const float* Wl  = (const float*)d_in[4];
    const float* bl  = (const float*)d_in[5];
    const float* Wh  = (const float*)d_in[6];
    const float* bh  = (const float*)d_in[7];
    const float* Wr  = (const float*)d_in[8];
    const float* br  = (const float*)d_in[9];
    float* out = (float*)d_out;

    int n = in_sizes[0] / D;      // nodes
    int e = in_sizes[2];          // edges
    int nb = (n + SCAN_B - 1) / SCAN_B;

    wt_kernel<<<(D * TWO_D + 255) / 256, 256>>>(Wr);
    gate_kernel<<<(n * 32 + 255) / 256, 256>>>(h, Wl, Wh, n);

    // CSR build
    zero_deg_kernel<<<(n + 255) / 256, 256>>>(n);
    hist_kernel<<<(e + 255) / 256, 256>>>(dst, e);
    scan1_kernel<<<nb, SCAN_B>>>(n);
    scan2_kernel<<<1, 1024>>>(nb);
    scan3_kernel<<<(n + 255) / 256, 256>>>(n);
    fill_kernel<<<(e + 255) / 256, 256>>>(dn, src, dst, bl, bh, e);

    // Gather aggregation (one warp per node)
    gather_kernel<<<(int)(((size_t)n * 32 + 255) / 256), 256>>>(h, n);

    // Output projection
    out_kernel<<<(n + NB - 1) / NB, 256>>>(br, out, n);
}

// round 5
// speedup vs baseline: 6.0011x; 1.0625x over previous
#include <cuda_runtime.h>
#include <math.h>

#define MAX_N 100000
#define MAX_E 1600000
#define D 64
#define TWO_D 128
#define NB 64
#define SCAN_B 512

// Scratch (static __device__ arrays — no allocations allowed)
__device__ float4 g_gate[MAX_N];                 // (low_dst, low_src, high_dst, high_src)
__device__ float  g_z[(size_t)MAX_N * TWO_D];    // [N, 2D] aggregation (z_low | z_high)
__device__ float  g_WrT[TWO_D * D];              // Wr transposed
__device__ int    g_deg[MAX_N];                  // in-degree per node
__device__ int    g_start[MAX_N];                // CSR row start (exclusive scan)
__device__ int    g_cursor[MAX_N];               // fill cursors
__device__ int    g_bsum[(MAX_N + SCAN_B - 1) / SCAN_B + 1];
__device__ int    g_esrc[MAX_E];                 // dst-grouped src indices

// ---------------------------------------------------------------------------
// Prep: transpose Wr AND zero in-degree counters (fused, one launch).
// ---------------------------------------------------------------------------
__global__ void prep_kernel(const float* __restrict__ Wr, int n)
{
    int i = blockIdx.x * blockDim.x + threadIdx.x;
    if (i < D * TWO_D) {
        int j = i >> 7;
        int k = i & 127;
        g_WrT[k * D + j] = Wr[i];
    }
    if (i < n) g_deg[i] = 0;
}

// ---------------------------------------------------------------------------
// Gate projections: one warp per node.
// ---------------------------------------------------------------------------
__global__ void gate_kernel(const float* __restrict__ h,
                            const float* __restrict__ Wl,
                            const float* __restrict__ Wh,
                            int n)
{
    int warp = (blockIdx.x * blockDim.x + threadIdx.x) >> 5;
    int lane = threadIdx.x & 31;
    if (warp >= n) return;

    const float* hp = h + (size_t)warp * D;
    float a0 = hp[lane];
    float a1 = hp[lane + 32];

    float ld = a0 * Wl[lane]      + a1 * Wl[lane + 32];
    float ls = a0 * Wl[lane + 64] + a1 * Wl[lane + 96];
    float hd = a0 * Wh[lane]      + a1 * Wh[lane + 32];
    float hs = a0 * Wh[lane + 64] + a1 * Wh[lane + 96];

    #pragma unroll
    for (int off = 16; off; off >>= 1) {
        ld += __shfl_xor_sync(0xFFFFFFFFu, ld, off);
        ls += __shfl_xor_sync(0xFFFFFFFFu, ls, off);
        hd += __shfl_xor_sync(0xFFFFFFFFu, hd, off);
        hs += __shfl_xor_sync(0xFFFFFFFFu, hs, off);
    }
    if (lane == 0) g_gate[warp] = make_float4(ld, ls, hd, hs);
}

// ---------------------------------------------------------------------------
// Histogram of dst (vectorized int4 loads, 4 atomics/thread).
// ---------------------------------------------------------------------------
__global__ void hist_kernel(const int* __restrict__ dst, int e)
{
    int i = blockIdx.x * blockDim.x + threadIdx.x;
    int e4 = e >> 2;
    if (i < e4) {
        int4 d4 = reinterpret_cast<const int4*>(dst)[i];
        atomicAdd(&g_deg[d4.x], 1);
        atomicAdd(&g_deg[d4.y], 1);
        atomicAdd(&g_deg[d4.z], 1);
        atomicAdd(&g_deg[d4.w], 1);
    }
    // tail
    int t = e4 * 4 + i;
    if (i < (e & 3)) {
        // handled only by first few threads: indices e4*4 .. e-1
        atomicAdd(&g_deg[dst[t]], 1);
    }
}

// ---------------------------------------------------------------------------
// 3-kernel exclusive scan over g_deg -> g_start (+cursor copy).
// ---------------------------------------------------------------------------
__global__ void scan1_kernel(int n)
{
    __shared__ int sh[SCAN_B];
    int tid = threadIdx.x;
    int i = blockIdx.x * SCAN_B + tid;
    int v = (i < n) ? g_deg[i] : 0;
    sh[tid] = v;
    __syncthreads();
    #pragma unroll
    for (int off = 1; off < SCAN_B; off <<= 1) {
        int t = (tid >= off) ? sh[tid - off] : 0;
        __syncthreads();
        sh[tid] += t;
        __syncthreads();
    }
    if (i < n) g_start[i] = sh[tid] - v;
    if (tid == SCAN_B - 1) g_bsum[blockIdx.x] = sh[tid];
}

__global__ void scan2_kernel(int nb)
{
    __shared__ int sh[1024];
    int tid = threadIdx.x;
    int v = (tid < nb) ? g_bsum[tid] : 0;
    sh[tid] = v;
    __syncthreads();
    #pragma unroll
    for (int off = 1; off < 1024; off <<= 1) {
        int t = (tid >= off) ? sh[tid - off] : 0;
        __syncthreads();
        sh[tid] += t;
        __syncthreads();
    }
    if (tid < nb) g_bsum[tid] = sh[tid] - v;
}

__global__ void scan3_kernel(int n)
{
    int i = blockIdx.x * blockDim.x + threadIdx.x;
    if (i < n) {
        int s = g_start[i] + g_bsum[i / SCAN_B];
        g_start[i] = s;
        g_cursor[i] = s;
    }
}

// ---------------------------------------------------------------------------
// Fill: permute src into dst-grouped CSR order (one thread per edge).
// ---------------------------------------------------------------------------
__global__ void fill_kernel(const int* __restrict__ src,
                            const int* __restrict__ dst,
                            int e)
{
    int i = blockIdx.x * blockDim.x + threadIdx.x;
    if (i >= e) return;
    int pos = atomicAdd(&g_cursor[dst[i]], 1);
    g_esrc[pos] = src[i];
}

// ---------------------------------------------------------------------------
// Gather-aggregate: one warp per node, coef computed in-lane, no atomics.
// Lane l owns h components l and l+32 for both low and high halves.
// ---------------------------------------------------------------------------
__global__ void gather_kernel(const float* __restrict__ h,
                              const float* __restrict__ dnorm,
                              const float* __restrict__ bl,
                              const float* __restrict__ bh,
                              int n)
{
    int warp = (blockIdx.x * blockDim.x + threadIdx.x) >> 5;
    int lane = threadIdx.x & 31;
    if (warp >= n) return;

    int start = g_start[warp];
    int deg   = g_deg[warp];
    int end   = start + deg;

    float4 gt  = g_gate[warp];   // warp-uniform broadcast
    float dn_t = dnorm[warp];
    float bl0  = bl[0];
    float bh0  = bh[0];

    float zl0 = 0.f, zl1 = 0.f, zh0 = 0.f, zh1 = 0.f;

    for (int base = start; base < end; base += 32) {
        int my = base + lane;
        int msrc = 0;
        float mel = 0.f, meh = 0.f;
        if (my < end) {
            msrc = g_esrc[my];
            float4 gs = g_gate[msrc];
            float xl = gt.x + gs.y + bl0;
            float xh = gt.z + gs.w + bh0;
            float gl =  tanhf(xl > 0.f ? xl : -0.5f * xl);
            float gh = -tanhf(xh > 0.f ? xh : -0.5f * xh);
            float dd = dn_t * dnorm[msrc];
            mel = gl * dd;
            meh = gh * dd;
        }
        int cnt = min(32, end - base);

        int i = 0;
        for (; i + 4 <= cnt; i += 4) {
            int s0 = __shfl_sync(0xFFFFFFFFu, msrc, i);
            int s1 = __shfl_sync(0xFFFFFFFFu, msrc, i + 1);
            int s2 = __shfl_sync(0xFFFFFFFFu, msrc, i + 2);
            int s3 = __shfl_sync(0xFFFFFFFFu, msrc, i + 3);
            float cl0 = __shfl_sync(0xFFFFFFFFu, mel, i);
            float ch0 = __shfl_sync(0xFFFFFFFFu, meh, i);
            float cl1 = __shfl_sync(0xFFFFFFFFu, mel, i + 1);
            float ch1 = __shfl_sync(0xFFFFFFFFu, meh, i + 1);
            float cl2 = __shfl_sync(0xFFFFFFFFu, mel, i + 2);
            float ch2 = __shfl_sync(0xFFFFFFFFu, meh, i + 2);
            float cl3 = __shfl_sync(0xFFFFFFFFu, mel, i + 3);
            float ch3 = __shfl_sync(0xFFFFFFFFu, meh, i + 3);

            const float* p0 = h + (size_t)s0 * D;
            const float* p1 = h + (size_t)s1 * D;
            const float* p2 = h + (size_t)s2 * D;
            const float* p3 = h + (size_t)s3 * D;
            float a0 = p0[lane], b0 = p0[lane + 32];
            float a1 = p1[lane], b1 = p1[lane + 32];
            float a2 = p2[lane], b2 = p2[lane + 32];
            float a3 = p3[lane], b3 = p3[lane + 32];

            zl0 = fmaf(a0, cl0, zl0); zl1 = fmaf(b0, cl0, zl1);
            zh0 = fmaf(a0, ch0, zh0); zh1 = fmaf(b0, ch0, zh1);
            zl0 = fmaf(a1, cl1, zl0); zl1 = fmaf(b1, cl1, zl1);
            zh0 = fmaf(a1, ch1, zh0); zh1 = fmaf(b1, ch1, zh1);
            zl0 = fmaf(a2, cl2, zl0); zl1 = fmaf(b2, cl2, zl1);
            zh0 = fmaf(a2, ch2, zh0); zh1 = fmaf(b2, ch2, zh1);
            zl0 = fmaf(a3, cl3, zl0); zl1 = fmaf(b3, cl3, zl1);
            zh0 = fmaf(a3, ch3, zh0); zh1 = fmaf(b3, ch3, zh1);
        }
        for (; i < cnt; i++) {
            int s0 = __shfl_sync(0xFFFFFFFFu, msrc, i);
            float cl = __shfl_sync(0xFFFFFFFFu, mel, i);
            float ch = __shfl_sync(0xFFFFFFFFu, meh, i);
            const float* p0 = h + (size_t)s0 * D;
            float a0 = p0[lane], b0 = p0[lane + 32];
            zl0 = fmaf(a0, cl, zl0); zl1 = fmaf(b0, cl, zl1);
            zh0 = fmaf(a0, ch, zh0); zh1 = fmaf(b0, ch, zh1);
        }
    }

    float* z = g_z + (size_t)warp * TWO_D;
    z[lane]      = zl0;
    z[lane + 32] = zl1;
    z[lane + 64] = zh0;
    z[lane + 96] = zh1;
}

// ---------------------------------------------------------------------------
// Output projection, register-blocked 4x4.
// ---------------------------------------------------------------------------
__global__ void __launch_bounds__(256) out_kernel(const float* __restrict__ br,
                                                  float* __restrict__ out,
                                                  int n)
{
    __shared__ float sW[TWO_D * D];
    __shared__ float sZ[NB * TWO_D];

    int tid = threadIdx.x;
    int node0 = blockIdx.x * NB;

    {
        const float4* Wg = reinterpret_cast<const float4*>(g_WrT);
        float4* Ws = reinterpret_cast<float4*>(sW);
        #pragma unroll
        for (int i = tid; i < (TWO_D * D) / 4; i += 256)
            Ws[i] = Wg[i];
    }
    {
        const float4* Zg = reinterpret_cast<const float4*>(g_z) + (size_t)node0 * (TWO_D / 4);
        float4* Zs = reinterpret_cast<float4*>(sZ);
        #pragma unroll
        for (int i = tid; i < NB * (TWO_D / 4); i += 256) {
            int node = node0 + i / (TWO_D / 4);
            Zs[i] = (node < n) ? Zg[i] : make_float4(0.f, 0.f, 0.f, 0.f);
        }
    }
    __syncthreads();

    int jg = tid & 15;
    int ng = tid >> 4;

    float acc[4][4];
    #pragma unroll
    for (int i = 0; i < 4; i++)
        #pragma unroll
        for (int jj = 0; jj < 4; jj++)
            acc[i][jj] = 0.f;

    const float4* sW4 = reinterpret_cast<const float4*>(sW);
    const float* zbase = sZ + ng * 4 * TWO_D;

    #pragma unroll 4
    for (int k = 0; k < TWO_D; k++) {
        float4 w = sW4[k * (D / 4) + jg];
        float z0 = zbase[0 * TWO_D + k];
        float z1 = zbase[1 * TWO_D + k];
        float z2 = zbase[2 * TWO_D + k];
        float z3 = zbase[3 * TWO_D + k];
        acc[0][0] = fmaf(z0, w.x, acc[0][0]); acc[0][1] = fmaf(z0, w.y, acc[0][1]);
        acc[0][2] = fmaf(z0, w.z, acc[0][2]); acc[0][3] = fmaf(z0, w.w, acc[0][3]);
        acc[1][0] = fmaf(z1, w.x, acc[1][0]); acc[1][1] = fmaf(z1, w.y, acc[1][1]);
        acc[1][2] = fmaf(z1, w.z, acc[1][2]); acc[1][3] = fmaf(z1, w.w, acc[1][3]);
        acc[2][0] = fmaf(z2, w.x, acc[2][0]); acc[2][1] = fmaf(z2, w.y, acc[2][1]);
        acc[2][2] = fmaf(z2, w.z, acc[2][2]); acc[2][3] = fmaf(z2, w.w, acc[2][3]);
        acc[3][0] = fmaf(z3, w.x, acc[3][0]); acc[3][1] = fmaf(z3, w.y, acc[3][1]);
        acc[3][2] = fmaf(z3, w.z, acc[3][2]); acc[3][3] = fmaf(z3, w.w, acc[3][3]);
    }

    int j = jg * 4;
    float4 b4 = *reinterpret_cast<const float4*>(br + j);
    #pragma unroll
    for (int i = 0; i < 4; i++) {
        int node = node0 + ng * 4 + i;
        if (node < n) {
            float4 o;
            o.x = acc[i][0] + b4.x;
            o.y = acc[i][1] + b4.y;
            o.z = acc[i][2] + b4.z;
            o.w = acc[i][3] + b4.w;
            *reinterpret_cast<float4*>(out + (size_t)node * D + j) = o;
        }
    }
}

// ---------------------------------------------------------------------------
extern "C" void kernel_launch(void* const* d_in, const int* in_sizes, int n_in,
                              void* d_out, int out_size)
{
    const float* h   = (const float*)d_in[0];
    const float* dn  = (const float*)d_in[1];
    const int*   src = (const int*)  d_in[2];
    const int*   dst = (const int*)  d_in[3];
    const float* Wl  = (const float*)d_in[4];
    const float* bl  = (const float*)d_in[5];
    const float* Wh  = (const float*)d_in[6];
    const float* bh  = (const float*)d_in[7];
    const float* Wr  = (const float*)d_in[8];
    const float* br  = (const float*)d_in[9];
    float* out = (float*)d_out;

    int n = in_sizes[0] / D;      // nodes
    int e = in_sizes[2];          // edges
    int nb = (n + SCAN_B - 1) / SCAN_B;

    int prep_threads = (n > D * TWO_D) ? n : D * TWO_D;
    prep_kernel<<<(prep_threads + 255) / 256, 256>>>(Wr, n);
    gate_kernel<<<(n * 32 + 255) / 256, 256>>>(h, Wl, Wh, n);

    // CSR build
    hist_kernel<<<((e >> 2) + 255) / 256, 256>>>(dst, e);
    scan1_kernel<<<nb, SCAN_B>>>(n);
    scan2_kernel<<<1, 1024>>>(nb);
    scan3_kernel<<<(n + 255) / 256, 256>>>(n);
    fill_kernel<<<(e + 255) / 256, 256>>>(src, dst, e);

    // Gather aggregation (one warp per node, fused coef)
    gather_kernel<<<(int)(((size_t)n * 32 + 255) / 256), 256>>>(h, dn, bl, bh, n);

    // Output projection
    out_kernel<<<(n + NB - 1) / NB, 256>>>(br, out, n);
}